// round 14
// baseline (speedup 1.0000x reference)
#include <cuda_runtime.h>
#include <cuda_bf16.h>

#define BB   8
#define NN   32768
#define KK   20
#define CHN  16
#define NPTS (BB * 32768)

#define L2E 1.44269504088896f   // log2(e)
#define ZSH 20.0f               // fixed softmax shift (range guard, shift-invariant)

// 8 lanes per point: lane = (hi, q). Iteration kp: hi=0 -> k=2kp, hi=1 -> k=2kp+1;
// q = channel quarter [4q,4q+4). Coop gather: lane l8 loads k = l8, l8+8,
// (l8+16 if l8<4), broadcast by shfl. Each lane's eo[4] is its 16B store chunk
// -> warp STG.128 covers 4 FULL 128B lines.
// 64-thread blocks, 21 blocks/SM: 42 warps/SM (full 48-reg RF ceiling) vs 40
// with 128-thread blocks; cheaper barriers and smoother tail waves.
__global__ void __launch_bounds__(64, 21)
gap_kernel(const float* __restrict__ x,
           const int*   __restrict__ idx32,
           const float* __restrict__ w1,  const float* __restrict__ g1,
           const float* __restrict__ b1,  const float* __restrict__ m1,
           const float* __restrict__ v1,
           const float* __restrict__ w2,  const float* __restrict__ g2,
           const float* __restrict__ b2,  const float* __restrict__ m2,
           const float* __restrict__ v2,
           const float* __restrict__ w1n, const float* __restrict__ g1n,
           const float* __restrict__ b1n, const float* __restrict__ m1n,
           const float* __restrict__ v1n,
           const float* __restrict__ w2n, const float* __restrict__ g2n,
           const float* __restrict__ b2n, const float* __restrict__ m2n,
           const float* __restrict__ v2n,
           float* __restrict__ out, float* __restrict__ edge_o)
{
    // ---- fold BN into affine constants ----
    __shared__ float sA1[CHN], sB1[CHN], sC1[CHN], sW2[CHN];
    __shared__ float sAn[CHN], sBn[CHN], sCn[CHN], sWn[CHN];
    __shared__ float sZC;

    int t = threadIdx.x;
    if (t < CHN) {
        float s1 = g1[t] * rsqrtf(v1[t] + 1e-5f);
        sA1[t] = w1[2*t]     * s1;
        sB1[t] = w1[2*t + 1] * s1;
        sC1[t] = b1[t] - m1[t] * s1;
        float s2 = g2[0] * rsqrtf(v2[0] + 1e-5f);
        sW2[t] = w2[t] * s2;

        float s1n = g1n[t] * rsqrtf(v1n[t] + 1e-5f);
        sAn[t] = w1n[2*t]     * s1n;
        sBn[t] = w1n[2*t + 1] * s1n;
        sCn[t] = b1n[t] - m1n[t] * s1n;
        float s2n = g2n[0] * rsqrtf(v2n[0] + 1e-5f);
        sWn[t] = w2n[t] * s2n;

        if (t == 0) {
            float c2  = b2[0]  - m2[0]  * (g2[0]  * rsqrtf(v2[0]  + 1e-5f));
            float c2n = b2n[0] - m2n[0] * (g2n[0] * rsqrtf(v2n[0] + 1e-5f));
            sZC = c2 + c2n;
        }
    }

    // ---- merged idx-width detect (warp 1; 256B, L2-broadcast) ----
    // odd words of first 32 little-endian int64 elems all zero <=> int64 idx.
    unsigned int oddw = 0;
    if (t >= 32) oddw = ((const unsigned int*)idx32)[2 * (t - 32) + 1];
    int sh = __syncthreads_or(oddw != 0) ? 0 : 1;   // 1 -> int64 idx

    int g   = blockIdx.x * 64 + t;
    int p   = g >> 3;                   // point id (8 lanes per point)
    int l8  = t & 7;                    // lane within 8-lane point group
    int q   = t & 3;                    // channel quarter
    int hi  = (t >> 2) & 1;             // k parity handled by this lane
    int c0  = q << 2;
    int b   = p >> 15;                  // N = 2^15
    int n   = p & 32767;
    int gb  = (t & 31) & 24;            // group base lane (for shfl source)

    const float* xrow = x + b * NN;
    float xc = __ldg(xrow + n);         // 4 consecutive addrs per group -> 1 line

    // per-thread folded constants for this quarter's 4 channels
    float A1h[4], D1h[4], Anh[4], Dnh[4], W2h[4], Wnh[4];
#pragma unroll
    for (int c = 0; c < 4; c++) {
        int cc = c0 + c;
        A1h[c] = sA1[cc];
        D1h[c] = fmaf(sB1[cc], xc, sC1[cc]);
        Anh[c] = sAn[cc];
        Dnh[c] = fmaf(sBn[cc], xc, sCn[cc]);
        W2h[c] = sW2[cc];
        Wnh[c] = sWn[cc];
    }
    float zc = sZC;

    // ---- cooperative gather: lane l8 loads k = l8, l8+8, (l8+16 iff l8<4) ----
    float xr[3];
    {
        int i0, i1;
        if (sh) {                       // int64: word index 2*(20p + k)
            const int* ipb = idx32 + (size_t)p * (2 * KK) + 2 * l8;
            i0 = __ldg(ipb + 0);
            i1 = __ldg(ipb + 16);
            if (l8 < 4) {
                int i2 = __ldg(ipb + 32);
                xr[2] = __ldg(xrow + i2);   // only lanes 0-3 issue these
            }
        } else {                        // int32
            const int* ipb = idx32 + (size_t)p * KK + l8;
            i0 = __ldg(ipb + 0);
            i1 = __ldg(ipb + 8);
            if (l8 < 4) {
                int i2 = __ldg(ipb + 16);
                xr[2] = __ldg(xrow + i2);
            }
        }
        xr[0] = __ldg(xrow + i0);
        xr[1] = __ldg(xrow + i1);
    }

    float acc[4];
#pragma unroll
    for (int c = 0; c < 4; c++) acc[c] = 0.0f;
    float ssum = 0.0f;

    float* ep = edge_o + (size_t)p * (KK * CHN);   // this point's 1280B block

#pragma unroll
    for (int kp = 0; kp < KK / 2; kp++) {
        int klane = 2 * kp + hi;        // this lane's k
        // broadcast xv[klane] from the group lane that gathered it
        float xvk = __shfl_sync(0xffffffffu, xr[kp >> 2], gb | (klane & 7));
        float d = xvk - xc;

        float eo[4];
        float s = 0.0f;
#pragma unroll
        for (int c = 0; c < 4; c++) {
            float t1 = fmaf(A1h[c], d, D1h[c]);
            t1 = fmaxf(t1, 0.2f * t1);          // lrelu
            s  = fmaf(W2h[c], t1, s);
            float tn = fmaf(Anh[c], d, Dnh[c]);
            tn = fmaxf(tn, 0.2f * tn);
            eo[c] = tn;
            s  = fmaf(Wnh[c], tn, s);
        }
        // reduce the 4 quarters' partial logits (within the 4-lane k-subgroup)
        s += __shfl_xor_sync(0xffffffffu, s, 1);
        s += __shfl_xor_sync(0xffffffffu, s, 2);
        float z = zc + s;
        z = fmaxf(z, 0.2f * z);                 // lrelu(a+e)

        // fixed-shift softmax numerator
        float pk = exp2f(fmaf(z, L2E, -(ZSH * L2E)));
        ssum += pk;
#pragma unroll
        for (int c = 0; c < 4; c++)
            acc[c] = fmaf(pk, eo[c], acc[c]);

        // coalesced store: warp covers 4 points x 128B FULL lines
        __stcs((float4*)(ep + kp * 32 + l8 * 4), make_float4(eo[0], eo[1], eo[2], eo[3]));
    }

    // ---- combine the two k-parity halves (lane l <-> l^4) ----
    ssum += __shfl_xor_sync(0xffffffffu, ssum, 4);
#pragma unroll
    for (int c = 0; c < 4; c++)
        acc[c] += __shfl_xor_sync(0xffffffffu, acc[c], 4);

    if (hi == 0) {                      // lanes 0-3 of each group write 64B
        float inv = 1.0f / ssum;
        float* op = out + (size_t)p * CHN + c0;
        __stcs((float4*)op, make_float4(acc[0]*inv, acc[1]*inv, acc[2]*inv, acc[3]*inv));
    }
}

extern "C" void kernel_launch(void* const* d_in, const int* in_sizes, int n_in,
                              void* d_out, int out_size) {
    const float* x    = (const float*)d_in[0];
    // d_in[1] = pos (unused), d_in[3] = dis (unused)
    const int*   idx  = (const int*)d_in[2];
    const float* w1   = (const float*)d_in[4];
    const float* g1   = (const float*)d_in[5];
    const float* b1   = (const float*)d_in[6];
    const float* m1   = (const float*)d_in[7];
    const float* v1   = (const float*)d_in[8];
    const float* w2   = (const float*)d_in[9];
    const float* g2   = (const float*)d_in[10];
    const float* b2   = (const float*)d_in[11];
    const float* m2   = (const float*)d_in[12];
    const float* v2   = (const float*)d_in[13];
    const float* w1n  = (const float*)d_in[14];
    const float* g1n  = (const float*)d_in[15];
    const float* b1n  = (const float*)d_in[16];
    const float* m1n  = (const float*)d_in[17];
    const float* v1n  = (const float*)d_in[18];
    const float* w2n  = (const float*)d_in[19];
    const float* g2n  = (const float*)d_in[20];
    const float* b2n  = (const float*)d_in[21];
    const float* m2n  = (const float*)d_in[22];
    const float* v2n  = (const float*)d_in[23];

    float* out  = (float*)d_out;                         // (B,N,CH) first
    float* edge = out + (size_t)NPTS * CHN;              // then (B,N,K,CH)

    // single kernel: width-detect merged; 8 lanes per point; 64-thread blocks
    gap_kernel<<<(NPTS * 8) / 64, 64>>>(x, idx,
                                    w1, g1, b1, m1, v1, w2, g2, b2, m2, v2,
                                    w1n, g1n, b1n, m1n, v1n, w2n, g2n, b2n, m2n, v2n,
                                    out, edge);
}

// round 15
// speedup vs baseline: 1.4970x; 1.4970x over previous
#include <cuda_runtime.h>
#include <cuda_bf16.h>

#define BB   8
#define NN   32768
#define KK   20
#define CHN  16
#define NPTS (BB * 32768)

#define L2E 1.44269504088896f   // log2(e)
#define ZSH 20.0f               // fixed softmax shift (range guard, shift-invariant)

// FINAL (R12 config — best measured: 61.7us, equal-best plateau 61.5-61.7):
// 8 lanes per point: lane = (hi, q). Iteration kp: hi=0 -> k=2kp, hi=1 -> k=2kp+1;
// q = channel quarter [4q,4q+4). Coop gather: lane l8 loads k = l8, l8+8,
// (l8+16 if l8<4), broadcast by shfl. Each lane's eo[4] is its 16B store chunk
// -> warp STG.128 covers 4 FULL 128B lines. Fixed-shift softmax (1 exp2/k).
// Idx width detect merged into the kernel via the weight-fold barrier.
__global__ void __launch_bounds__(128, 10)
gap_kernel(const float* __restrict__ x,
           const int*   __restrict__ idx32,
           const float* __restrict__ w1,  const float* __restrict__ g1,
           const float* __restrict__ b1,  const float* __restrict__ m1,
           const float* __restrict__ v1,
           const float* __restrict__ w2,  const float* __restrict__ g2,
           const float* __restrict__ b2,  const float* __restrict__ m2,
           const float* __restrict__ v2,
           const float* __restrict__ w1n, const float* __restrict__ g1n,
           const float* __restrict__ b1n, const float* __restrict__ m1n,
           const float* __restrict__ v1n,
           const float* __restrict__ w2n, const float* __restrict__ g2n,
           const float* __restrict__ b2n, const float* __restrict__ m2n,
           const float* __restrict__ v2n,
           float* __restrict__ out, float* __restrict__ edge_o)
{
    // ---- fold BN into affine constants ----
    __shared__ float sA1[CHN], sB1[CHN], sC1[CHN], sW2[CHN];
    __shared__ float sAn[CHN], sBn[CHN], sCn[CHN], sWn[CHN];
    __shared__ float sZC;

    int t = threadIdx.x;
    if (t < CHN) {
        float s1 = g1[t] * rsqrtf(v1[t] + 1e-5f);
        sA1[t] = w1[2*t]     * s1;
        sB1[t] = w1[2*t + 1] * s1;
        sC1[t] = b1[t] - m1[t] * s1;
        float s2 = g2[0] * rsqrtf(v2[0] + 1e-5f);
        sW2[t] = w2[t] * s2;

        float s1n = g1n[t] * rsqrtf(v1n[t] + 1e-5f);
        sAn[t] = w1n[2*t]     * s1n;
        sBn[t] = w1n[2*t + 1] * s1n;
        sCn[t] = b1n[t] - m1n[t] * s1n;
        float s2n = g2n[0] * rsqrtf(v2n[0] + 1e-5f);
        sWn[t] = w2n[t] * s2n;

        if (t == 0) {
            float c2  = b2[0]  - m2[0]  * (g2[0]  * rsqrtf(v2[0]  + 1e-5f));
            float c2n = b2n[0] - m2n[0] * (g2n[0] * rsqrtf(v2n[0] + 1e-5f));
            sZC = c2 + c2n;
        }
    }

    // ---- merged idx-width detect (warp 0 only; 256B, L2-broadcast) ----
    // odd words of first 32 little-endian int64 elems all zero <=> int64 idx.
    unsigned int oddw = 0;
    if (t < 32) oddw = ((const unsigned int*)idx32)[2 * t + 1];
    int sh = __syncthreads_or(oddw != 0) ? 0 : 1;   // 1 -> int64 idx

    int g   = blockIdx.x * 128 + t;
    int p   = g >> 3;                   // point id (8 lanes per point)
    int l8  = t & 7;                    // lane within 8-lane point group
    int q   = t & 3;                    // channel quarter
    int hi  = (t >> 2) & 1;             // k parity handled by this lane
    int c0  = q << 2;
    int b   = p >> 15;                  // N = 2^15
    int n   = p & 32767;
    int gb  = (t & 31) & 24;            // group base lane (for shfl source)

    const float* xrow = x + b * NN;
    float xc = __ldg(xrow + n);         // 4 consecutive addrs per warp -> 1 line

    // per-thread folded constants for this quarter's 4 channels
    float A1h[4], D1h[4], Anh[4], Dnh[4], W2h[4], Wnh[4];
#pragma unroll
    for (int c = 0; c < 4; c++) {
        int cc = c0 + c;
        A1h[c] = sA1[cc];
        D1h[c] = fmaf(sB1[cc], xc, sC1[cc]);
        Anh[c] = sAn[cc];
        Dnh[c] = fmaf(sBn[cc], xc, sCn[cc]);
        W2h[c] = sW2[cc];
        Wnh[c] = sWn[cc];
    }
    float zc = sZC;

    // ---- cooperative gather: lane l8 loads k = l8, l8+8, (l8+16 iff l8<4) ----
    float xr[3];
    {
        int i0, i1;
        if (sh) {                       // int64: word index 2*(20p + k)
            const int* ipb = idx32 + (size_t)p * (2 * KK) + 2 * l8;
            i0 = __ldg(ipb + 0);
            i1 = __ldg(ipb + 16);
            if (l8 < 4) {
                int i2 = __ldg(ipb + 32);
                xr[2] = __ldg(xrow + i2);   // only lanes 0-3 issue these
            }
        } else {                        // int32
            const int* ipb = idx32 + (size_t)p * KK + l8;
            i0 = __ldg(ipb + 0);
            i1 = __ldg(ipb + 8);
            if (l8 < 4) {
                int i2 = __ldg(ipb + 16);
                xr[2] = __ldg(xrow + i2);
            }
        }
        xr[0] = __ldg(xrow + i0);
        xr[1] = __ldg(xrow + i1);
    }

    float acc[4];
#pragma unroll
    for (int c = 0; c < 4; c++) acc[c] = 0.0f;
    float ssum = 0.0f;

    float* ep = edge_o + (size_t)p * (KK * CHN);   // this point's 1280B block

#pragma unroll
    for (int kp = 0; kp < KK / 2; kp++) {
        int klane = 2 * kp + hi;        // this lane's k
        // broadcast xv[klane] from the group lane that gathered it
        float xvk = __shfl_sync(0xffffffffu, xr[kp >> 2], gb | (klane & 7));
        float d = xvk - xc;

        float eo[4];
        float s = 0.0f;
#pragma unroll
        for (int c = 0; c < 4; c++) {
            float t1 = fmaf(A1h[c], d, D1h[c]);
            t1 = fmaxf(t1, 0.2f * t1);          // lrelu
            s  = fmaf(W2h[c], t1, s);
            float tn = fmaf(Anh[c], d, Dnh[c]);
            tn = fmaxf(tn, 0.2f * tn);
            eo[c] = tn;
            s  = fmaf(Wnh[c], tn, s);
        }
        // reduce the 4 quarters' partial logits (within the 4-lane k-subgroup)
        s += __shfl_xor_sync(0xffffffffu, s, 1);
        s += __shfl_xor_sync(0xffffffffu, s, 2);
        float z = zc + s;
        z = fmaxf(z, 0.2f * z);                 // lrelu(a+e)

        // fixed-shift softmax numerator
        float pk = exp2f(fmaf(z, L2E, -(ZSH * L2E)));
        ssum += pk;
#pragma unroll
        for (int c = 0; c < 4; c++)
            acc[c] = fmaf(pk, eo[c], acc[c]);

        // coalesced store: warp covers 4 points x 128B FULL lines
        __stcs((float4*)(ep + kp * 32 + l8 * 4), make_float4(eo[0], eo[1], eo[2], eo[3]));
    }

    // ---- combine the two k-parity halves (lane l <-> l^4) ----
    ssum += __shfl_xor_sync(0xffffffffu, ssum, 4);
#pragma unroll
    for (int c = 0; c < 4; c++)
        acc[c] += __shfl_xor_sync(0xffffffffu, acc[c], 4);

    if (hi == 0) {                      // lanes 0-3 of each group write 64B
        float inv = 1.0f / ssum;
        float* op = out + (size_t)p * CHN + c0;
        __stcs((float4*)op, make_float4(acc[0]*inv, acc[1]*inv, acc[2]*inv, acc[3]*inv));
    }
}

extern "C" void kernel_launch(void* const* d_in, const int* in_sizes, int n_in,
                              void* d_out, int out_size) {
    const float* x    = (const float*)d_in[0];
    // d_in[1] = pos (unused), d_in[3] = dis (unused)
    const int*   idx  = (const int*)d_in[2];
    const float* w1   = (const float*)d_in[4];
    const float* g1   = (const float*)d_in[5];
    const float* b1   = (const float*)d_in[6];
    const float* m1   = (const float*)d_in[7];
    const float* v1   = (const float*)d_in[8];
    const float* w2   = (const float*)d_in[9];
    const float* g2   = (const float*)d_in[10];
    const float* b2   = (const float*)d_in[11];
    const float* m2   = (const float*)d_in[12];
    const float* v2   = (const float*)d_in[13];
    const float* w1n  = (const float*)d_in[14];
    const float* g1n  = (const float*)d_in[15];
    const float* b1n  = (const float*)d_in[16];
    const float* m1n  = (const float*)d_in[17];
    const float* v1n  = (const float*)d_in[18];
    const float* w2n  = (const float*)d_in[19];
    const float* g2n  = (const float*)d_in[20];
    const float* b2n  = (const float*)d_in[21];
    const float* m2n  = (const float*)d_in[22];
    const float* v2n  = (const float*)d_in[23];

    float* out  = (float*)d_out;                         // (B,N,CH) first
    float* edge = out + (size_t)NPTS * CHN;              // then (B,N,K,CH)

    // single kernel: width-detect merged; 8 lanes per point; 128-thread blocks
    gap_kernel<<<(NPTS * 8) / 128, 128>>>(x, idx,
                                    w1, g1, b1, m1, v1, w2, g2, b2, m2, v2,
                                    w1n, g1n, b1n, m1n, v1n, w2n, g2n, b2n, m2n, v2n,
                                    out, edge);
}

// round 16
// speedup vs baseline: 1.5239x; 1.0180x over previous
#include <cuda_runtime.h>
#include <cuda_bf16.h>

#define BB   8
#define NN   32768
#define KK   20
#define CHN  16
#define NPTS (BB * 32768)

#define L2E 1.44269504088896f   // log2(e)
#define ZSH 20.0f               // fixed softmax shift (range guard, shift-invariant)

// FINAL (R12-family champion; plateau 61.5-61.7us, noise band ~1.5us):
// 8 lanes per point: lane = (hi, q). Iteration kp: hi=0 -> k=2kp, hi=1 -> k=2kp+1;
// q = channel quarter [4q,4q+4). Coop gather: lane l8 loads k = l8, l8+8,
// (l8+16 if l8<4), broadcast by shfl. Each lane's eo[4] is its 16B store chunk
// -> warp STG.128 covers 4 FULL 128B lines. Fixed-shift softmax (1 exp2/k).
// Idx width detect merged into the kernel via the weight-fold barrier.
// Micro-trim: zc is pre-divided by 4 and seeded into each lane's partial
// logit sum, deleting one FADD per kp.
__global__ void __launch_bounds__(128, 10)
gap_kernel(const float* __restrict__ x,
           const int*   __restrict__ idx32,
           const float* __restrict__ w1,  const float* __restrict__ g1,
           const float* __restrict__ b1,  const float* __restrict__ m1,
           const float* __restrict__ v1,
           const float* __restrict__ w2,  const float* __restrict__ g2,
           const float* __restrict__ b2,  const float* __restrict__ m2,
           const float* __restrict__ v2,
           const float* __restrict__ w1n, const float* __restrict__ g1n,
           const float* __restrict__ b1n, const float* __restrict__ m1n,
           const float* __restrict__ v1n,
           const float* __restrict__ w2n, const float* __restrict__ g2n,
           const float* __restrict__ b2n, const float* __restrict__ m2n,
           const float* __restrict__ v2n,
           float* __restrict__ out, float* __restrict__ edge_o)
{
    // ---- fold BN into affine constants ----
    __shared__ float sA1[CHN], sB1[CHN], sC1[CHN], sW2[CHN];
    __shared__ float sAn[CHN], sBn[CHN], sCn[CHN], sWn[CHN];
    __shared__ float sZC4;              // (c2 + c2n) / 4, seeded per q-lane

    int t = threadIdx.x;
    if (t < CHN) {
        float s1 = g1[t] * rsqrtf(v1[t] + 1e-5f);
        sA1[t] = w1[2*t]     * s1;
        sB1[t] = w1[2*t + 1] * s1;
        sC1[t] = b1[t] - m1[t] * s1;
        float s2 = g2[0] * rsqrtf(v2[0] + 1e-5f);
        sW2[t] = w2[t] * s2;

        float s1n = g1n[t] * rsqrtf(v1n[t] + 1e-5f);
        sAn[t] = w1n[2*t]     * s1n;
        sBn[t] = w1n[2*t + 1] * s1n;
        sCn[t] = b1n[t] - m1n[t] * s1n;
        float s2n = g2n[0] * rsqrtf(v2n[0] + 1e-5f);
        sWn[t] = w2n[t] * s2n;

        if (t == 0) {
            float c2  = b2[0]  - m2[0]  * (g2[0]  * rsqrtf(v2[0]  + 1e-5f));
            float c2n = b2n[0] - m2n[0] * (g2n[0] * rsqrtf(v2n[0] + 1e-5f));
            sZC4 = 0.25f * (c2 + c2n);
        }
    }

    // ---- merged idx-width detect (warp 0 only; 256B, L2-broadcast) ----
    // odd words of first 32 little-endian int64 elems all zero <=> int64 idx.
    unsigned int oddw = 0;
    if (t < 32) oddw = ((const unsigned int*)idx32)[2 * t + 1];
    int sh = __syncthreads_or(oddw != 0) ? 0 : 1;   // 1 -> int64 idx

    int g   = blockIdx.x * 128 + t;
    int p   = g >> 3;                   // point id (8 lanes per point)
    int l8  = t & 7;                    // lane within 8-lane point group
    int q   = t & 3;                    // channel quarter
    int hi  = (t >> 2) & 1;             // k parity handled by this lane
    int c0  = q << 2;
    int b   = p >> 15;                  // N = 2^15
    int n   = p & 32767;
    int gb  = (t & 31) & 24;            // group base lane (for shfl source)

    const float* xrow = x + b * NN;
    float xc = __ldg(xrow + n);         // 4 consecutive addrs per warp -> 1 line

    // per-thread folded constants for this quarter's 4 channels
    float A1h[4], D1h[4], Anh[4], Dnh[4], W2h[4], Wnh[4];
#pragma unroll
    for (int c = 0; c < 4; c++) {
        int cc = c0 + c;
        A1h[c] = sA1[cc];
        D1h[c] = fmaf(sB1[cc], xc, sC1[cc]);
        Anh[c] = sAn[cc];
        Dnh[c] = fmaf(sBn[cc], xc, sCn[cc]);
        W2h[c] = sW2[cc];
        Wnh[c] = sWn[cc];
    }
    float zseed = sZC4;                 // per-lane share of the logit constant

    // ---- cooperative gather: lane l8 loads k = l8, l8+8, (l8+16 iff l8<4) ----
    float xr[3];
    {
        int i0, i1;
        if (sh) {                       // int64: word index 2*(20p + k)
            const int* ipb = idx32 + (size_t)p * (2 * KK) + 2 * l8;
            i0 = __ldg(ipb + 0);
            i1 = __ldg(ipb + 16);
            if (l8 < 4) {
                int i2 = __ldg(ipb + 32);
                xr[2] = __ldg(xrow + i2);   // only lanes 0-3 issue these
            }
        } else {                        // int32
            const int* ipb = idx32 + (size_t)p * KK + l8;
            i0 = __ldg(ipb + 0);
            i1 = __ldg(ipb + 8);
            if (l8 < 4) {
                int i2 = __ldg(ipb + 16);
                xr[2] = __ldg(xrow + i2);
            }
        }
        xr[0] = __ldg(xrow + i0);
        xr[1] = __ldg(xrow + i1);
    }

    float acc[4];
#pragma unroll
    for (int c = 0; c < 4; c++) acc[c] = 0.0f;
    float ssum = 0.0f;

    float* ep = edge_o + (size_t)p * (KK * CHN);   // this point's 1280B block

#pragma unroll
    for (int kp = 0; kp < KK / 2; kp++) {
        int klane = 2 * kp + hi;        // this lane's k
        // broadcast xv[klane] from the group lane that gathered it
        float xvk = __shfl_sync(0xffffffffu, xr[kp >> 2], gb | (klane & 7));
        float d = xvk - xc;

        float eo[4];
        float s = zseed;                // zc folded into the 4-lane reduction
#pragma unroll
        for (int c = 0; c < 4; c++) {
            float t1 = fmaf(A1h[c], d, D1h[c]);
            t1 = fmaxf(t1, 0.2f * t1);          // lrelu
            s  = fmaf(W2h[c], t1, s);
            float tn = fmaf(Anh[c], d, Dnh[c]);
            tn = fmaxf(tn, 0.2f * tn);
            eo[c] = tn;
            s  = fmaf(Wnh[c], tn, s);
        }
        // reduce the 4 quarters' partial logits (within the 4-lane k-subgroup)
        s += __shfl_xor_sync(0xffffffffu, s, 1);
        s += __shfl_xor_sync(0xffffffffu, s, 2);
        float z = fmaxf(s, 0.2f * s);           // lrelu(a+e)

        // fixed-shift softmax numerator
        float pk = exp2f(fmaf(z, L2E, -(ZSH * L2E)));
        ssum += pk;
#pragma unroll
        for (int c = 0; c < 4; c++)
            acc[c] = fmaf(pk, eo[c], acc[c]);

        // coalesced store: warp covers 4 points x 128B FULL lines
        __stcs((float4*)(ep + kp * 32 + l8 * 4), make_float4(eo[0], eo[1], eo[2], eo[3]));
    }

    // ---- combine the two k-parity halves (lane l <-> l^4) ----
    ssum += __shfl_xor_sync(0xffffffffu, ssum, 4);
#pragma unroll
    for (int c = 0; c < 4; c++)
        acc[c] += __shfl_xor_sync(0xffffffffu, acc[c], 4);

    if (hi == 0) {                      // lanes 0-3 of each group write 64B
        float inv = 1.0f / ssum;
        float* op = out + (size_t)p * CHN + c0;
        __stcs((float4*)op, make_float4(acc[0]*inv, acc[1]*inv, acc[2]*inv, acc[3]*inv));
    }
}

extern "C" void kernel_launch(void* const* d_in, const int* in_sizes, int n_in,
                              void* d_out, int out_size) {
    const float* x    = (const float*)d_in[0];
    // d_in[1] = pos (unused), d_in[3] = dis (unused)
    const int*   idx  = (const int*)d_in[2];
    const float* w1   = (const float*)d_in[4];
    const float* g1   = (const float*)d_in[5];
    const float* b1   = (const float*)d_in[6];
    const float* m1   = (const float*)d_in[7];
    const float* v1   = (const float*)d_in[8];
    const float* w2   = (const float*)d_in[9];
    const float* g2   = (const float*)d_in[10];
    const float* b2   = (const float*)d_in[11];
    const float* m2   = (const float*)d_in[12];
    const float* v2   = (const float*)d_in[13];
    const float* w1n  = (const float*)d_in[14];
    const float* g1n  = (const float*)d_in[15];
    const float* b1n  = (const float*)d_in[16];
    const float* m1n  = (const float*)d_in[17];
    const float* v1n  = (const float*)d_in[18];
    const float* w2n  = (const float*)d_in[19];
    const float* g2n  = (const float*)d_in[20];
    const float* b2n  = (const float*)d_in[21];
    const float* m2n  = (const float*)d_in[22];
    const float* v2n  = (const float*)d_in[23];

    float* out  = (float*)d_out;                         // (B,N,CH) first
    float* edge = out + (size_t)NPTS * CHN;              // then (B,N,K,CH)

    // single kernel: width-detect merged; 8 lanes per point; 128-thread blocks
    gap_kernel<<<(NPTS * 8) / 128, 128>>>(x, idx,
                                    w1, g1, b1, m1, v1, w2, g2, b2, m2, v2,
                                    w1n, g1n, b1n, m1n, v1n, w2n, g2n, b2n, m2n, v2n,
                                    out, edge);
}